// round 16
// baseline (speedup 1.0000x reference)
#include <cuda_runtime.h>
#include <math_constants.h>
#include <cstdint>

// NonMaxSuppression: 3x3 max-pool NMS mask on (8,1,2048,2048) fp32.
// out[y][x] = 1.0f iff in[y][x] == max3x3(in, y, x)  (pad -inf)
//             && in[y][x] >= 0.6f
//             && 10 <= y < H-10 && 10 <= x < W-10
//
// R16 (= R15 + missing <cstdint>): cp.async (LDGSTS) smem-ring pipeline.
// Register-based variants (R2-R14) cap per-SM in-flight bytes at ~24KB
// (regs bound MLP), leaving DRAM at 61-67% with nothing else saturated =
// queue-starved memory system. Each warp streams its 128-col strip through
// a depth-8 smem ring via cp.async (in-flight tracked in the LSU, not
// registers): 5 rows x 512B x 32 warps = 80KB/SM in flight. Halos
// (including segment-edge words) are cp.async'd into the ring too ->
// NO shfl, NO edge LDGs, tiny reg count.

#define H 2048
#define W 2048
#define ROWS 32
#define REP_THR 0.6f
#define BORDER 10
#define D 8            // smem ring depth (rows per warp)
#define ROWB 544       // 12B pad + left halo word @12 + 512B data @16 + right halo @528

__global__ __launch_bounds__(128, 8)
void nms_kernel(const float* __restrict__ in, float* __restrict__ out) {
    __shared__ __align__(16) char smem_raw[4 * D * ROWB];

    const int lane = threadIdx.x;                 // 0..31
    const int warp = threadIdx.y;                 // 0..3
    const int seg  = blockIdx.x * 4 + warp;       // 0..15
    const int b    = blockIdx.z;
    const int y0   = blockIdx.y * ROWS;
    const int x4   = seg * 128 + lane * 4;

    const float* img = in  + (size_t)b * H * W;
    float*       o   = out + (size_t)b * H * W;

    char* wbase = smem_raw + warp * (D * ROWB);
    const unsigned int wbase_u =
        (unsigned int)__cvta_generic_to_shared(wbase);

    const bool hl = (seg > 0);     // left halo col exists (lane 0's x4-1)
    const bool hr = (seg < 15);    // right halo col exists (lane 31's x4+4)

    // Image-edge halo cells are never written by cp.async: preset -inf once.
    if (!hl && lane == 0) {
        #pragma unroll
        for (int s = 0; s < D; ++s)
            *reinterpret_cast<float*>(wbase + s * ROWB + 12) = -CUDART_INF_F;
    }
    if (!hr && lane == 31) {
        #pragma unroll
        for (int s = 0; s < D; ++s)
            *reinterpret_cast<float*>(wbase + s * ROWB + 528) = -CUDART_INF_F;
    }
    __syncwarp();

    // Issue row j (gmem row y0-1+j, clamped) into ring slot j%D, one group.
    auto issue_row = [&](int j) {
        int y  = y0 - 1 + j;
        int yy = y < 0 ? 0 : (y >= H ? H - 1 : y);
        const float* row = img + (size_t)yy * W + x4;
        unsigned int slot = wbase_u + (j % D) * ROWB;
        asm volatile("cp.async.ca.shared.global [%0], [%1], 16;"
                     :: "r"(slot + 16 + lane * 16), "l"(row) : "memory");
        if (lane == 0 && hl)
            asm volatile("cp.async.ca.shared.global [%0], [%1], 4;"
                         :: "r"(slot + 12), "l"(row - 1) : "memory");
        if (lane == 31 && hr)
            asm volatile("cp.async.ca.shared.global [%0], [%1], 4;"
                         :: "r"(slot + 528), "l"(row + 4) : "memory");
        asm volatile("cp.async.commit_group;" ::: "memory");
    };

    // Consume row j from smem: horizontal 3-max + center values. Pure LDS.
    auto consume = [&](int j, float4& hm, float4& v) {
        const char* slot = wbase + (j % D) * ROWB;
        const float* c = reinterpret_cast<const float*>(slot + 16 + lane * 16);
        v = *reinterpret_cast<const float4*>(c);
        float l = c[-1];
        float r = c[4];
        hm.x = fmaxf(l,   fmaxf(v.x, v.y));
        hm.y = fmaxf(v.x, fmaxf(v.y, v.z));
        hm.z = fmaxf(v.y, fmaxf(v.z, v.w));
        hm.w = fmaxf(v.z, fmaxf(v.w, r));
    };

    // Prologue: issue rows 0..D-2 (7 groups); rows 0,1 must be complete.
    #pragma unroll
    for (int j = 0; j < D - 1; ++j) issue_row(j);
    asm volatile("cp.async.wait_group %0;" :: "n"(D - 3) : "memory");  // >=2 done
    __syncwarp();

    float4 hm_m, hm_c, v_tmp, v_cur;
    consume(0, hm_m, v_tmp);
    consume(1, hm_c, v_cur);

    const bool bx0 = (x4 + 0 >= BORDER) && (x4 + 0 < W - BORDER);
    const bool bx1 = (x4 + 1 >= BORDER) && (x4 + 1 < W - BORDER);
    const bool bx2 = (x4 + 2 >= BORDER) && (x4 + 2 < W - BORDER);
    const bool bx3 = (x4 + 3 >= BORDER) && (x4 + 3 < W - BORDER);

    for (int k = 0; k < ROWS; ++k) {
        // Keep the ring full: issue row k+D-1 (or an empty group to keep
        // the wait_group count consistent).
        int jn = k + D - 1;
        if (jn <= ROWS + 1) issue_row(jn);
        else asm volatile("cp.async.commit_group;" ::: "memory");

        // Groups issued = k+8; all but last 5 done => rows 0..k+2 complete.
        asm volatile("cp.async.wait_group %0;" :: "n"(D - 3) : "memory");
        __syncwarp();

        float4 hm_p, v_n;
        consume(k + 2, hm_p, v_n);

        const int y = y0 + k;
        const bool by = (y >= BORDER) && (y < H - BORDER);

        float4 res;
        {
            float m;
            m = fmaxf(hm_m.x, fmaxf(hm_c.x, hm_p.x));
            res.x = (by && bx0 && v_cur.x >= REP_THR && v_cur.x == m) ? 1.0f : 0.0f;
            m = fmaxf(hm_m.y, fmaxf(hm_c.y, hm_p.y));
            res.y = (by && bx1 && v_cur.y >= REP_THR && v_cur.y == m) ? 1.0f : 0.0f;
            m = fmaxf(hm_m.z, fmaxf(hm_c.z, hm_p.z));
            res.z = (by && bx2 && v_cur.z >= REP_THR && v_cur.z == m) ? 1.0f : 0.0f;
            m = fmaxf(hm_m.w, fmaxf(hm_c.w, hm_p.w));
            res.w = (by && bx3 && v_cur.w >= REP_THR && v_cur.w == m) ? 1.0f : 0.0f;
        }

        __stcs(reinterpret_cast<float4*>(o + (size_t)y * W + x4), res);

        hm_m  = hm_c;
        hm_c  = hm_p;
        v_cur = v_n;
    }

    // Drain outstanding async copies before exit.
    asm volatile("cp.async.wait_group 0;" ::: "memory");
}

extern "C" void kernel_launch(void* const* d_in, const int* in_sizes, int n_in,
                              void* d_out, int out_size) {
    const float* in = (const float*)d_in[0];
    float* out = (float*)d_out;
    (void)in_sizes; (void)n_in; (void)out_size;

    dim3 block(32, 4);                 // 4 warps, each owns a 128-col segment
    dim3 grid(16 / 4, H / ROWS, 8);    // 4 x 64 x 8 = 2048 blocks
    nms_kernel<<<grid, block>>>(in, out);
}